// round 9
// baseline (speedup 1.0000x reference)
#include <cuda_runtime.h>
#include <cuda_fp16.h>

#define NP 1000000
#define NPIL 30000

typedef unsigned long long ull;
typedef unsigned int u32;

__device__ __forceinline__ ull pack2(float lo, float hi) {
    ull r; asm("mov.b64 %0,{%1,%2};" : "=l"(r) : "f"(lo), "f"(hi)); return r;
}
__device__ __forceinline__ void unpack2(ull v, float& lo, float& hi) {
    asm("mov.b64 {%0,%1},%2;" : "=f"(lo), "=f"(hi) : "l"(v));
}
__device__ __forceinline__ ull ffma2(ull a, ull b, ull c) {
    ull d; asm("fma.rn.f32x2 %0,%1,%2,%3;" : "=l"(d) : "l"(a), "l"(b), "l"(c)); return d;
}
__device__ __forceinline__ u32 s2u(const void* p) {
    return (u32)__cvta_generic_to_shared(p);
}

// ---------------- scratch ----------------
__device__ float d_W1f[7 * 32];
__device__ float d_t1[32];
__device__ float d_W2f[64 * 32];
__device__ float d_t2[32];
__device__ __half d_W2ah[32 * 32];     // folded W2a, transposed [n][k] fp16
__device__ int   d_count[NPIL];
__device__ int   d_offset[NPIL];
__device__ int   d_galloc;
__device__ int   d_pos[NP];
__device__ int   d_idx[NP];
__device__ __align__(16) u32 d_ha[(size_t)NP * 32];  // fp16 [h(32)|a(32)] = 128B/row

// ---------------- init ----------------
__global__ void k_init(const float* __restrict__ W1, const float* __restrict__ g1,
                       const float* __restrict__ b1, const float* __restrict__ m1,
                       const float* __restrict__ v1, const float* __restrict__ W2,
                       const float* __restrict__ g2, const float* __restrict__ b2,
                       const float* __restrict__ m2, const float* __restrict__ v2) {
    int i = blockIdx.x * blockDim.x + threadIdx.x;
    if (i < NPIL) d_count[i] = 0;
    if (i == 0) d_galloc = 0;
    if (blockIdx.x == 0 && threadIdx.x < 32) {
        int j = threadIdx.x;
        float s1 = g1[j] * rsqrtf(v1[j] + 1e-3f);
        d_t1[j] = b1[j] - m1[j] * s1;
        for (int k = 0; k < 7; k++) d_W1f[k * 32 + j] = W1[k * 32 + j] * s1;
        float s2 = g2[j] * rsqrtf(v2[j] + 1e-3f);
        d_t2[j] = b2[j] - m2[j] * s2;
        for (int k = 0; k < 64; k++) d_W2f[k * 32 + j] = W2[k * 32 + j] * s2;
        for (int k = 0; k < 32; k++)
            d_W2ah[j * 32 + k] = __float2half(W2[k * 32 + j] * s2);
    }
}

// ---------------- histogram + per-point rank ----------------
__global__ void k_hist(const int* __restrict__ unq) {
    int i = blockIdx.x * blockDim.x + threadIdx.x;
    if (i < NP / 4) {
        int4 v = ((const int4*)unq)[i];
        int4 r;
        r.x = atomicAdd(&d_count[v.x], 1);
        r.y = atomicAdd(&d_count[v.y], 1);
        r.z = atomicAdd(&d_count[v.z], 1);
        r.w = atomicAdd(&d_count[v.w], 1);
        ((int4*)d_pos)[i] = r;
    }
}

// ---------------- segment allocation ----------------
__global__ __launch_bounds__(256) void k_alloc() {
    __shared__ int wsum[8], wpre[8], sbase;
    int t = threadIdx.x, lane = t & 31, w = t >> 5;
    int i = blockIdx.x * 256 + t;
    int c = (i < NPIL) ? d_count[i] : 0;
    int incl = c;
#pragma unroll
    for (int d = 1; d < 32; d <<= 1) {
        int v = __shfl_up_sync(0xffffffffu, incl, d);
        if (lane >= d) incl += v;
    }
    if (lane == 31) wsum[w] = incl;
    __syncthreads();
    if (w == 0 && lane < 8) {
        int s = wsum[lane];
        int inc = s;
#pragma unroll
        for (int d = 1; d < 8; d <<= 1) {
            int v = __shfl_up_sync(0xffu, inc, d);
            if (lane >= d) inc += v;
        }
        wpre[lane] = inc - s;
        if (lane == 7) sbase = atomicAdd(&d_galloc, inc);
    }
    __syncthreads();
    if (i < NPIL) d_offset[i] = sbase + wpre[w] + (incl - c);
}

// ---------------- scatter point indices (4B writes), overlapped with pass1 ----------------
__global__ void k_sidx(const int* __restrict__ unq) {
    int i = blockIdx.x * blockDim.x + threadIdx.x;
    if (i < NP / 4) {
        int4 u = ((const int4*)unq)[i];
        int4 r = ((const int4*)d_pos)[i];
        int b = i * 4;
        d_idx[d_offset[u.x] + r.x] = b + 0;
        d_idx[d_offset[u.y] + r.y] = b + 1;
        d_idx[d_offset[u.z] + r.z] = b + 2;
        d_idx[d_offset[u.w] + r.w] = b + 3;
    }
}

// ---------------- pass 1: scalar h, tensor-core a, coalesced [h|a] fp16 store ----------------
__global__ __launch_bounds__(128) void k_pass1(const float* __restrict__ pts,
                                               const float* __restrict__ fc) {
    __shared__ ull swp[112];                 // W1f packed pairs
    __shared__ ull st1[16];
    __shared__ __half sWa[32 * 40];          // [n][k] fp16, stride 40 halves
    __shared__ float sT2[32];
    __shared__ __align__(16) __half sh[128 * 72];   // 18 KB staging
    int t = threadIdx.x;
    if (t < 112) { float2 w = ((const float2*)d_W1f)[t]; swp[t] = pack2(w.x, w.y); }
    if (t < 16)  { float2 v = ((const float2*)d_t1)[t];  st1[t] = pack2(v.x, v.y); }
    for (int q = t; q < 1024; q += 128) sWa[(q >> 5) * 40 + (q & 31)] = d_W2ah[q];
    if (t < 32) sT2[t] = d_t2[t];

    // coalesced input staging into sh-as-float: [0:640) = pts block, [640:1024) = fc block
    float* sfin = reinterpret_cast<float*>(sh);
    {
        size_t b5 = (size_t)blockIdx.x * 640;
        size_t l5 = (size_t)NP * 5 - 1;
#pragma unroll
        for (int q = 0; q < 5; q++) {
            size_t o = b5 + q * 128 + t;
            sfin[q * 128 + t] = pts[o > l5 ? l5 : o];
        }
        size_t b3 = (size_t)blockIdx.x * 384;
        size_t l3 = (size_t)NP * 3 - 1;
#pragma unroll
        for (int q = 0; q < 3; q++) {
            size_t o = b3 + q * 128 + t;
            sfin[640 + q * 128 + t] = fc[o > l3 ? l3 : o];
        }
    }
    __syncthreads();

    float f[7];
    f[0] = sfin[640 + t * 3 + 0];
    f[1] = sfin[640 + t * 3 + 1];
    f[2] = sfin[640 + t * 3 + 2];
    f[3] = sfin[t * 5 + 1];
    f[4] = sfin[t * 5 + 2];
    f[5] = sfin[t * 5 + 3];
    f[6] = sfin[t * 5 + 4];
    __syncthreads();                          // inputs consumed; sh can be reused

    int lane = t & 31, wid = t >> 5;

    // ---- scalar h = relu(feat @ W1f + t1), f32x2 packed ----
    ull h2[16];
#pragma unroll
    for (int j = 0; j < 16; j++) h2[j] = st1[j];
#pragma unroll
    for (int k = 0; k < 7; k++) {
        ull fk = pack2(f[k], f[k]);
#pragma unroll
        for (int j = 0; j < 16; j++) h2[j] = ffma2(swp[k * 16 + j], fk, h2[j]);
    }
    u32* mr32 = reinterpret_cast<u32*>(&sh[t * 72]);
#pragma unroll
    for (int q = 0; q < 16; q++) {
        float lo, hi;
        unpack2(h2[q], lo, hi);
        __half2 p = __floats2half2_rn(fmaxf(lo, 0.f), fmaxf(hi, 0.f));
        mr32[q] = *reinterpret_cast<u32*>(&p);
    }
    __syncwarp();

    // ---- B fragments: W2a fp16 [n][k], once per warp ----
    u32 bfr[4][2][2];
    u32 wb = s2u(sWa);
#pragma unroll
    for (int nt = 0; nt < 4; nt++)
#pragma unroll
        for (int q = 0; q < 2; q++) {
            u32 addr = wb + (((nt * 8 + (lane & 7)) * 40 + q * 16 + ((lane & 8) ? 8 : 0)) << 1);
            asm volatile("ldmatrix.sync.aligned.m8n8.x2.shared.b16 {%0,%1},[%2];"
                         : "=r"(bfr[nt][q][0]), "=r"(bfr[nt][q][1]) : "r"(addr));
        }
    float t2lo[4], t2hi[4];
#pragma unroll
    for (int nt = 0; nt < 4; nt++) {
        t2lo[nt] = sT2[nt * 8 + 2 * (lane & 3)];
        t2hi[nt] = sT2[nt * 8 + 2 * (lane & 3) + 1];
    }

    // ---- tensor-core a = h @ W2a + t2 for this warp's 32 points ----
    u32 shb = s2u(sh);
#pragma unroll
    for (int tile = 0; tile < 2; tile++) {
        int p0 = wid * 32 + tile * 16;
        u32 a[2][4];
#pragma unroll
        for (int q = 0; q < 2; q++) {
            int r = p0 + (lane & 7) + ((lane & 8) ? 8 : 0);
            int colh = q * 16 + ((lane & 16) ? 8 : 0);
            u32 addr = shb + ((r * 72 + colh) << 1);
            asm volatile("ldmatrix.sync.aligned.m8n8.x4.shared.b16 {%0,%1,%2,%3},[%4];"
                         : "=r"(a[q][0]), "=r"(a[q][1]), "=r"(a[q][2]), "=r"(a[q][3])
                         : "r"(addr));
        }
#pragma unroll
        for (int nt = 0; nt < 4; nt++) {
            float d0 = 0.f, d1 = 0.f, d2 = 0.f, d3 = 0.f;
            asm volatile("mma.sync.aligned.m16n8k16.row.col.f32.f16.f16.f32 "
                         "{%0,%1,%2,%3},{%4,%5,%6,%7},{%8,%9},{%0,%1,%2,%3};"
                         : "+f"(d0), "+f"(d1), "+f"(d2), "+f"(d3)
                         : "r"(a[0][0]), "r"(a[0][1]), "r"(a[0][2]), "r"(a[0][3]),
                           "r"(bfr[nt][0][0]), "r"(bfr[nt][0][1]));
            asm volatile("mma.sync.aligned.m16n8k16.row.col.f32.f16.f16.f32 "
                         "{%0,%1,%2,%3},{%4,%5,%6,%7},{%8,%9},{%0,%1,%2,%3};"
                         : "+f"(d0), "+f"(d1), "+f"(d2), "+f"(d3)
                         : "r"(a[1][0]), "r"(a[1][1]), "r"(a[1][2]), "r"(a[1][3]),
                           "r"(bfr[nt][1][0]), "r"(bfr[nt][1][1]));
            int c0 = nt * 8 + 2 * (lane & 3);
            __half2 plo = __floats2half2_rn(d0 + t2lo[nt], d1 + t2hi[nt]);
            __half2 phi = __floats2half2_rn(d2 + t2lo[nt], d3 + t2hi[nt]);
            *reinterpret_cast<u32*>(&sh[(p0 + (lane >> 2)) * 72 + 32 + c0]) =
                *reinterpret_cast<u32*>(&plo);
            *reinterpret_cast<u32*>(&sh[(p0 + 8 + (lane >> 2)) * 72 + 32 + c0]) =
                *reinterpret_cast<u32*>(&phi);
        }
    }
    __syncthreads();

    // ---- coalesced copy-out: 128 rows x 16 u64 ----
    const ull* src = reinterpret_cast<const ull*>(sh);
    ulonglong2* dst = reinterpret_cast<ulonglong2*>(d_ha);
    size_t b128 = (size_t)blockIdx.x * 1024;
#pragma unroll
    for (int g = 0; g < 1024; g += 128) {
        int e = g + t;
        size_t o = b128 + e;
        if (o < (size_t)NP * 8) {
            int p = e >> 3, w = (e & 7) * 2;
            dst[o] = *reinterpret_cast<const ulonglong2*>(&src[p * 18 + w]);
        }
    }
}

// ---------------- pass 2: warp/pillar single sweep over fp16 rows ----------------
__global__ __launch_bounds__(256) void k_pillar(float* __restrict__ out) {
    __shared__ float sWb[32 * 32];
    __shared__ float ssum[8][32];
    __shared__ float smax[8][32];

    int t = threadIdx.x;
    for (int q = t; q < 1024; q += 256) sWb[q] = d_W2f[1024 + q];
    __syncthreads();

    int warp = t >> 5;
    int j = t & 31;
    int p = blockIdx.x * 8 + warp;
    int off = d_offset[p];
    int cnt = d_count[p];
    if (cnt == 0) { out[p * 32 + j] = 0.f; return; }
    const int* ip = d_idx + off;
    const u32* ha = d_ha;

    float sx0 = 0.f, sy0 = 0.f, sx1 = 0.f, sy1 = 0.f;
    float mx = -1e30f, my = -1e30f;
    for (int rb = 0; rb < cnt; rb += 32) {
        int lim = min(32, cnt - rb);
        int myidx = (j < lim) ? ip[rb + j] : 0;
        int u = 0;
        for (; u + 4 <= lim; u += 4) {
            int r0 = __shfl_sync(0xffffffffu, myidx, u + 0);
            int r1 = __shfl_sync(0xffffffffu, myidx, u + 1);
            int r2 = __shfl_sync(0xffffffffu, myidx, u + 2);
            int r3 = __shfl_sync(0xffffffffu, myidx, u + 3);
            u32 w0 = ha[(size_t)r0 * 32 + j];
            u32 w1 = ha[(size_t)r1 * 32 + j];
            u32 w2 = ha[(size_t)r2 * 32 + j];
            u32 w3 = ha[(size_t)r3 * 32 + j];
            float2 f0 = __half22float2(*reinterpret_cast<__half2*>(&w0));
            float2 f1 = __half22float2(*reinterpret_cast<__half2*>(&w1));
            float2 f2 = __half22float2(*reinterpret_cast<__half2*>(&w2));
            float2 f3 = __half22float2(*reinterpret_cast<__half2*>(&w3));
            sx0 += f0.x; sy0 += f0.y; mx = fmaxf(mx, f0.x); my = fmaxf(my, f0.y);
            sx1 += f1.x; sy1 += f1.y; mx = fmaxf(mx, f1.x); my = fmaxf(my, f1.y);
            sx0 += f2.x; sy0 += f2.y; mx = fmaxf(mx, f2.x); my = fmaxf(my, f2.y);
            sx1 += f3.x; sy1 += f3.y; mx = fmaxf(mx, f3.x); my = fmaxf(my, f3.y);
        }
        for (; u < lim; u++) {
            int r0 = __shfl_sync(0xffffffffu, myidx, u);
            u32 w0 = ha[(size_t)r0 * 32 + j];
            float2 f0 = __half22float2(*reinterpret_cast<__half2*>(&w0));
            sx0 += f0.x; sy0 += f0.y; mx = fmaxf(mx, f0.x); my = fmaxf(my, f0.y);
        }
    }
    if (j < 16) {
        ssum[warp][2 * j + 0] = sx0 + sx1;
        ssum[warp][2 * j + 1] = sy0 + sy1;
    } else {
        smax[warp][2 * (j - 16) + 0] = mx;
        smax[warp][2 * (j - 16) + 1] = my;
    }
    __syncwarp();

    float pm = 0.f;
#pragma unroll
    for (int k = 0; k < 32; k++) pm = fmaf(ssum[warp][k], sWb[k * 32 + j], pm);
    pm /= (float)cnt;
    out[p * 32 + j] = fmaxf(smax[warp][j] + pm, 0.f);
}

// ---------------- launch: fork/join so the sort chain overlaps pass1 ----------------
extern "C" void kernel_launch(void* const* d_in, const int* in_sizes, int n_in,
                              void* d_out, int out_size) {
    const float* points   = (const float*)d_in[0];
    const float* f_center = (const float*)d_in[1];
    const int*   unq      = (const int*)d_in[2];
    const float* W1 = (const float*)d_in[3];
    const float* g1 = (const float*)d_in[4];
    const float* b1 = (const float*)d_in[5];
    const float* m1 = (const float*)d_in[6];
    const float* v1 = (const float*)d_in[7];
    const float* W2 = (const float*)d_in[8];
    const float* g2 = (const float*)d_in[9];
    const float* b2 = (const float*)d_in[10];
    const float* m2 = (const float*)d_in[11];
    const float* v2 = (const float*)d_in[12];

    cudaStream_t sA;
    cudaEvent_t e0, eA;
    cudaStreamCreateWithFlags(&sA, cudaStreamNonBlocking);
    cudaEventCreateWithFlags(&e0, cudaEventDisableTiming);
    cudaEventCreateWithFlags(&eA, cudaEventDisableTiming);

    k_init<<<(NPIL + 255) / 256, 256>>>(W1, g1, b1, m1, v1, W2, g2, b2, m2, v2);
    cudaEventRecord(e0, 0);
    cudaStreamWaitEvent(sA, e0, 0);

    k_hist<<<(NP / 4 + 255) / 256, 256, 0, sA>>>(unq);
    k_alloc<<<(NPIL + 255) / 256, 256, 0, sA>>>();
    k_sidx<<<(NP / 4 + 255) / 256, 256, 0, sA>>>(unq);
    cudaEventRecord(eA, sA);

    k_pass1<<<(NP + 127) / 128, 128>>>(points, f_center);   // concurrent with sA chain

    cudaStreamWaitEvent(0, eA, 0);
    k_pillar<<<NPIL / 8, 256>>>((float*)d_out);

    cudaStreamDestroy(sA);
    cudaEventDestroy(e0);
    cudaEventDestroy(eA);
}

// round 10
// speedup vs baseline: 1.1144x; 1.1144x over previous
#include <cuda_runtime.h>
#include <cuda_fp16.h>

#define NP 1000000
#define NPIL 30000

typedef unsigned long long ull;
typedef unsigned int u32;

__device__ __forceinline__ ull pack2(float lo, float hi) {
    ull r; asm("mov.b64 %0,{%1,%2};" : "=l"(r) : "f"(lo), "f"(hi)); return r;
}
__device__ __forceinline__ void unpack2(ull v, float& lo, float& hi) {
    asm("mov.b64 {%0,%1},%2;" : "=f"(lo), "=f"(hi) : "l"(v));
}
__device__ __forceinline__ ull ffma2(ull a, ull b, ull c) {
    ull d; asm("fma.rn.f32x2 %0,%1,%2,%3;" : "=l"(d) : "l"(a), "l"(b), "l"(c)); return d;
}
__device__ __forceinline__ u32 s2u(const void* p) {
    return (u32)__cvta_generic_to_shared(p);
}

// ---------------- scratch ----------------
__device__ float d_W1f[7 * 32];
__device__ float d_t1[32];
__device__ float d_W2f[64 * 32];
__device__ float d_t2[32];
__device__ __half d_W2ah[32 * 32];     // folded W2a, transposed [n][k] fp16
__device__ int   d_count[NPIL];
__device__ int   d_offset[NPIL];
__device__ int   d_galloc;
__device__ int   d_pos[NP];
__device__ __align__(16) u32 d_ha[(size_t)NP * 32];  // fp16 [h(32)|a(32)] rows, PILLAR-SORTED

// ---------------- init ----------------
__global__ void k_init(const float* __restrict__ W1, const float* __restrict__ g1,
                       const float* __restrict__ b1, const float* __restrict__ m1,
                       const float* __restrict__ v1, const float* __restrict__ W2,
                       const float* __restrict__ g2, const float* __restrict__ b2,
                       const float* __restrict__ m2, const float* __restrict__ v2) {
    int i = blockIdx.x * blockDim.x + threadIdx.x;
    if (i < NPIL) d_count[i] = 0;
    if (i == 0) d_galloc = 0;
    if (blockIdx.x == 0 && threadIdx.x < 32) {
        int j = threadIdx.x;
        float s1 = g1[j] * rsqrtf(v1[j] + 1e-3f);
        d_t1[j] = b1[j] - m1[j] * s1;
        for (int k = 0; k < 7; k++) d_W1f[k * 32 + j] = W1[k * 32 + j] * s1;
        float s2 = g2[j] * rsqrtf(v2[j] + 1e-3f);
        d_t2[j] = b2[j] - m2[j] * s2;
        for (int k = 0; k < 64; k++) d_W2f[k * 32 + j] = W2[k * 32 + j] * s2;
        for (int k = 0; k < 32; k++)
            d_W2ah[j * 32 + k] = __float2half(W2[k * 32 + j] * s2);
    }
}

// ---------------- histogram + per-point rank ----------------
__global__ void k_hist(const int* __restrict__ unq) {
    int i = blockIdx.x * blockDim.x + threadIdx.x;
    if (i < NP / 4) {
        int4 v = ((const int4*)unq)[i];
        int4 r;
        r.x = atomicAdd(&d_count[v.x], 1);
        r.y = atomicAdd(&d_count[v.y], 1);
        r.z = atomicAdd(&d_count[v.z], 1);
        r.w = atomicAdd(&d_count[v.w], 1);
        ((int4*)d_pos)[i] = r;
    }
}

// ---------------- segment allocation ----------------
__global__ __launch_bounds__(256) void k_alloc() {
    __shared__ int wsum[8], wpre[8], sbase;
    int t = threadIdx.x, lane = t & 31, w = t >> 5;
    int i = blockIdx.x * 256 + t;
    int c = (i < NPIL) ? d_count[i] : 0;
    int incl = c;
#pragma unroll
    for (int d = 1; d < 32; d <<= 1) {
        int v = __shfl_up_sync(0xffffffffu, incl, d);
        if (lane >= d) incl += v;
    }
    if (lane == 31) wsum[w] = incl;
    __syncthreads();
    if (w == 0 && lane < 8) {
        int s = wsum[lane];
        int inc = s;
#pragma unroll
        for (int d = 1; d < 8; d <<= 1) {
            int v = __shfl_up_sync(0xffu, inc, d);
            if (lane >= d) inc += v;
        }
        wpre[lane] = inc - s;
        if (lane == 7) sbase = atomicAdd(&d_galloc, inc);
    }
    __syncthreads();
    if (i < NPIL) d_offset[i] = sbase + wpre[w] + (incl - c);
}

// ---------------- pass 1: scalar h, tensor-core a, warp-cooperative SORTED row scatter ----------
__global__ __launch_bounds__(128) void k_pass1(const float* __restrict__ pts,
                                               const float* __restrict__ fc,
                                               const int* __restrict__ unq) {
    __shared__ ull swp[112];                 // W1f packed pairs
    __shared__ ull st1[16];
    __shared__ __half sWa[32 * 40];          // [n][k] fp16, stride 40 halves
    __shared__ float sT2[32];
    __shared__ __align__(16) __half sh[128 * 72];   // 18 KB staging (72-half rows)
    int t = threadIdx.x;
    if (t < 112) { float2 w = ((const float2*)d_W1f)[t]; swp[t] = pack2(w.x, w.y); }
    if (t < 16)  { float2 v = ((const float2*)d_t1)[t];  st1[t] = pack2(v.x, v.y); }
    for (int q = t; q < 1024; q += 128) sWa[(q >> 5) * 40 + (q & 31)] = d_W2ah[q];
    if (t < 32) sT2[t] = d_t2[t];
    __syncthreads();

    int lane = t & 31, wid = t >> 5;
    int i = blockIdx.x * 128 + t;
    int ic = min(i, NP - 1);

    // destination row for this point (pillar-sorted); -1 for pad threads
    int mypos = -1;
    if (i < NP) mypos = d_offset[unq[i]] + d_pos[i];

    // ---- scalar h = relu(feat @ W1f + t1), f32x2 packed ----
    float f[7];
    f[0] = fc[ic * 3 + 0];
    f[1] = fc[ic * 3 + 1];
    f[2] = fc[ic * 3 + 2];
    f[3] = pts[ic * 5 + 1];
    f[4] = pts[ic * 5 + 2];
    f[5] = pts[ic * 5 + 3];
    f[6] = pts[ic * 5 + 4];
    ull h2[16];
#pragma unroll
    for (int j = 0; j < 16; j++) h2[j] = st1[j];
#pragma unroll
    for (int k = 0; k < 7; k++) {
        ull fk = pack2(f[k], f[k]);
#pragma unroll
        for (int j = 0; j < 16; j++) h2[j] = ffma2(swp[k * 16 + j], fk, h2[j]);
    }
    u32* mr32 = reinterpret_cast<u32*>(&sh[t * 72]);
#pragma unroll
    for (int q = 0; q < 16; q++) {
        float lo, hi;
        unpack2(h2[q], lo, hi);
        __half2 p = __floats2half2_rn(fmaxf(lo, 0.f), fmaxf(hi, 0.f));
        mr32[q] = *reinterpret_cast<u32*>(&p);
    }
    __syncwarp();

    // ---- B fragments: W2a fp16 [n][k], once per warp ----
    u32 bfr[4][2][2];
    u32 wb = s2u(sWa);
#pragma unroll
    for (int nt = 0; nt < 4; nt++)
#pragma unroll
        for (int q = 0; q < 2; q++) {
            u32 addr = wb + (((nt * 8 + (lane & 7)) * 40 + q * 16 + ((lane & 8) ? 8 : 0)) << 1);
            asm volatile("ldmatrix.sync.aligned.m8n8.x2.shared.b16 {%0,%1},[%2];"
                         : "=r"(bfr[nt][q][0]), "=r"(bfr[nt][q][1]) : "r"(addr));
        }
    float t2lo[4], t2hi[4];
#pragma unroll
    for (int nt = 0; nt < 4; nt++) {
        t2lo[nt] = sT2[nt * 8 + 2 * (lane & 3)];
        t2hi[nt] = sT2[nt * 8 + 2 * (lane & 3) + 1];
    }

    // ---- tensor-core a = h @ W2a + t2 for this warp's 32 points ----
    u32 shb = s2u(sh);
#pragma unroll
    for (int tile = 0; tile < 2; tile++) {
        int p0 = wid * 32 + tile * 16;
        u32 a[2][4];
#pragma unroll
        for (int q = 0; q < 2; q++) {
            int r = p0 + (lane & 7) + ((lane & 8) ? 8 : 0);
            int colh = q * 16 + ((lane & 16) ? 8 : 0);
            u32 addr = shb + ((r * 72 + colh) << 1);
            asm volatile("ldmatrix.sync.aligned.m8n8.x4.shared.b16 {%0,%1,%2,%3},[%4];"
                         : "=r"(a[q][0]), "=r"(a[q][1]), "=r"(a[q][2]), "=r"(a[q][3])
                         : "r"(addr));
        }
#pragma unroll
        for (int nt = 0; nt < 4; nt++) {
            float d0 = 0.f, d1 = 0.f, d2 = 0.f, d3 = 0.f;
            asm volatile("mma.sync.aligned.m16n8k16.row.col.f32.f16.f16.f32 "
                         "{%0,%1,%2,%3},{%4,%5,%6,%7},{%8,%9},{%0,%1,%2,%3};"
                         : "+f"(d0), "+f"(d1), "+f"(d2), "+f"(d3)
                         : "r"(a[0][0]), "r"(a[0][1]), "r"(a[0][2]), "r"(a[0][3]),
                           "r"(bfr[nt][0][0]), "r"(bfr[nt][0][1]));
            asm volatile("mma.sync.aligned.m16n8k16.row.col.f32.f16.f16.f32 "
                         "{%0,%1,%2,%3},{%4,%5,%6,%7},{%8,%9},{%0,%1,%2,%3};"
                         : "+f"(d0), "+f"(d1), "+f"(d2), "+f"(d3)
                         : "r"(a[1][0]), "r"(a[1][1]), "r"(a[1][2]), "r"(a[1][3]),
                           "r"(bfr[nt][1][0]), "r"(bfr[nt][1][1]));
            int c0 = nt * 8 + 2 * (lane & 3);
            __half2 plo = __floats2half2_rn(d0 + t2lo[nt], d1 + t2hi[nt]);
            __half2 phi = __floats2half2_rn(d2 + t2lo[nt], d3 + t2hi[nt]);
            *reinterpret_cast<u32*>(&sh[(p0 + (lane >> 2)) * 72 + 32 + c0]) =
                *reinterpret_cast<u32*>(&plo);
            *reinterpret_cast<u32*>(&sh[(p0 + 8 + (lane >> 2)) * 72 + 32 + c0]) =
                *reinterpret_cast<u32*>(&phi);
        }
    }
    __syncwarp();

    // ---- warp-cooperative scatter: one full 128B row per iteration (1 wavefront/row) ----
    const u32* srcw = reinterpret_cast<const u32*>(sh);
#pragma unroll
    for (int u = 0; u < 32; u++) {
        int pos = __shfl_sync(0xffffffffu, mypos, u);
        if (pos >= 0) {
            u32 v = srcw[(wid * 32 + u) * 36 + lane];      // 72 halves = 36 words/row
            d_ha[(size_t)pos * 32 + lane] = v;
        }
    }
}

// ---------------- pass 2: warp/pillar SEQUENTIAL stream over sorted fp16 rows ----------------
__global__ __launch_bounds__(256) void k_pillar(float* __restrict__ out) {
    __shared__ float sWb[32 * 32];
    __shared__ float ssum[8][32];
    __shared__ float smax[8][32];

    int t = threadIdx.x;
    for (int q = t; q < 1024; q += 256) sWb[q] = d_W2f[1024 + q];
    __syncthreads();

    int warp = t >> 5;
    int j = t & 31;
    int p = blockIdx.x * 8 + warp;                 // 3750 * 8 == 30000 exact
    int off = d_offset[p];
    int cnt = d_count[p];
    if (cnt == 0) { out[p * 32 + j] = 0.f; return; }
    const u32* base = d_ha + (size_t)off * 32 + j;

    float sx0 = 0.f, sy0 = 0.f, sx1 = 0.f, sy1 = 0.f;
    float mx = -1e30f, my = -1e30f;
    int r = 0;
    for (; r + 4 <= cnt; r += 4) {
        u32 w0 = base[(r + 0) * 32];
        u32 w1 = base[(r + 1) * 32];
        u32 w2 = base[(r + 2) * 32];
        u32 w3 = base[(r + 3) * 32];
        float2 f0 = __half22float2(*reinterpret_cast<__half2*>(&w0));
        float2 f1 = __half22float2(*reinterpret_cast<__half2*>(&w1));
        float2 f2 = __half22float2(*reinterpret_cast<__half2*>(&w2));
        float2 f3 = __half22float2(*reinterpret_cast<__half2*>(&w3));
        sx0 += f0.x; sy0 += f0.y; mx = fmaxf(mx, f0.x); my = fmaxf(my, f0.y);
        sx1 += f1.x; sy1 += f1.y; mx = fmaxf(mx, f1.x); my = fmaxf(my, f1.y);
        sx0 += f2.x; sy0 += f2.y; mx = fmaxf(mx, f2.x); my = fmaxf(my, f2.y);
        sx1 += f3.x; sy1 += f3.y; mx = fmaxf(mx, f3.x); my = fmaxf(my, f3.y);
    }
    for (; r < cnt; r++) {
        u32 w0 = base[r * 32];
        float2 f0 = __half22float2(*reinterpret_cast<__half2*>(&w0));
        sx0 += f0.x; sy0 += f0.y; mx = fmaxf(mx, f0.x); my = fmaxf(my, f0.y);
    }
    // lanes 0-15 carry h-pair sums (channels 2j, 2j+1); lanes 16-31 carry a-pair maxes
    if (j < 16) {
        ssum[warp][2 * j + 0] = sx0 + sx1;
        ssum[warp][2 * j + 1] = sy0 + sy1;
    } else {
        smax[warp][2 * (j - 16) + 0] = mx;
        smax[warp][2 * (j - 16) + 1] = my;
    }
    __syncwarp();

    float pm = 0.f;
#pragma unroll
    for (int k = 0; k < 32; k++) pm = fmaf(ssum[warp][k], sWb[k * 32 + j], pm);
    pm /= (float)cnt;
    out[p * 32 + j] = fmaxf(smax[warp][j] + pm, 0.f);
}

// ---------------- launch (serial chain; overlap removed — it regressed) ----------------
extern "C" void kernel_launch(void* const* d_in, const int* in_sizes, int n_in,
                              void* d_out, int out_size) {
    const float* points   = (const float*)d_in[0];
    const float* f_center = (const float*)d_in[1];
    const int*   unq      = (const int*)d_in[2];
    const float* W1 = (const float*)d_in[3];
    const float* g1 = (const float*)d_in[4];
    const float* b1 = (const float*)d_in[5];
    const float* m1 = (const float*)d_in[6];
    const float* v1 = (const float*)d_in[7];
    const float* W2 = (const float*)d_in[8];
    const float* g2 = (const float*)d_in[9];
    const float* b2 = (const float*)d_in[10];
    const float* m2 = (const float*)d_in[11];
    const float* v2 = (const float*)d_in[12];

    k_init<<<(NPIL + 255) / 256, 256>>>(W1, g1, b1, m1, v1, W2, g2, b2, m2, v2);
    k_hist<<<(NP / 4 + 255) / 256, 256>>>(unq);
    k_alloc<<<(NPIL + 255) / 256, 256>>>();
    k_pass1<<<(NP + 127) / 128, 128>>>(points, f_center, unq);
    k_pillar<<<NPIL / 8, 256>>>((float*)d_out);
}

// round 13
// speedup vs baseline: 1.1823x; 1.0610x over previous
#include <cuda_runtime.h>
#include <cuda_fp16.h>

#define NP 1000000
#define NPIL 30000

typedef unsigned long long ull;
typedef unsigned int u32;

__device__ __forceinline__ ull pack2(float lo, float hi) {
    ull r; asm("mov.b64 %0,{%1,%2};" : "=l"(r) : "f"(lo), "f"(hi)); return r;
}
__device__ __forceinline__ void unpack2(ull v, float& lo, float& hi) {
    asm("mov.b64 {%0,%1},%2;" : "=f"(lo), "=f"(hi) : "l"(v));
}
__device__ __forceinline__ ull ffma2(ull a, ull b, ull c) {
    ull d; asm("fma.rn.f32x2 %0,%1,%2,%3;" : "=l"(d) : "l"(a), "l"(b), "l"(c)); return d;
}
__device__ __forceinline__ u32 s2u(const void* p) {
    return (u32)__cvta_generic_to_shared(p);
}

// ---------------- scratch ----------------
__device__ float d_W1f[7 * 32];
__device__ float d_t1[32];
__device__ float d_W2f[64 * 32];
__device__ float d_t2[32];
__device__ __half d_W2ah[32 * 32];     // folded W2a, transposed [n][k] fp16
__device__ int   d_count[NPIL];
__device__ int   d_offset[NPIL];
__device__ int   d_galloc;
__device__ int   d_pos[NP];
__device__ __align__(16) u32 d_ha[(size_t)NP * 32];  // fp16 [h(32)|a(32)] rows, PILLAR-SORTED

// ---------------- init ----------------
__global__ void k_init(const float* __restrict__ W1, const float* __restrict__ g1,
                       const float* __restrict__ b1, const float* __restrict__ m1,
                       const float* __restrict__ v1, const float* __restrict__ W2,
                       const float* __restrict__ g2, const float* __restrict__ b2,
                       const float* __restrict__ m2, const float* __restrict__ v2) {
    int i = blockIdx.x * blockDim.x + threadIdx.x;
    if (i < NPIL) d_count[i] = 0;
    if (i == 0) d_galloc = 0;
    if (blockIdx.x == 0 && threadIdx.x < 32) {
        int j = threadIdx.x;
        float s1 = g1[j] * rsqrtf(v1[j] + 1e-3f);
        d_t1[j] = b1[j] - m1[j] * s1;
        for (int k = 0; k < 7; k++) d_W1f[k * 32 + j] = W1[k * 32 + j] * s1;
        float s2 = g2[j] * rsqrtf(v2[j] + 1e-3f);
        d_t2[j] = b2[j] - m2[j] * s2;
        for (int k = 0; k < 64; k++) d_W2f[k * 32 + j] = W2[k * 32 + j] * s2;
        for (int k = 0; k < 32; k++)
            d_W2ah[j * 32 + k] = __float2half(W2[k * 32 + j] * s2);
    }
}

// ---------------- histogram + per-point rank ----------------
__global__ void k_hist(const int* __restrict__ unq) {
    int i = blockIdx.x * blockDim.x + threadIdx.x;
    if (i < NP / 4) {
        int4 v = ((const int4*)unq)[i];
        int4 r;
        r.x = atomicAdd(&d_count[v.x], 1);
        r.y = atomicAdd(&d_count[v.y], 1);
        r.z = atomicAdd(&d_count[v.z], 1);
        r.w = atomicAdd(&d_count[v.w], 1);
        ((int4*)d_pos)[i] = r;
    }
}

// ---------------- segment allocation ----------------
__global__ __launch_bounds__(256) void k_alloc() {
    __shared__ int wsum[8], wpre[8], sbase;
    int t = threadIdx.x, lane = t & 31, w = t >> 5;
    int i = blockIdx.x * 256 + t;
    int c = (i < NPIL) ? d_count[i] : 0;
    int incl = c;
#pragma unroll
    for (int d = 1; d < 32; d <<= 1) {
        int v = __shfl_up_sync(0xffffffffu, incl, d);
        if (lane >= d) incl += v;
    }
    if (lane == 31) wsum[w] = incl;
    __syncthreads();
    if (w == 0 && lane < 8) {
        int s = wsum[lane];
        int inc = s;
#pragma unroll
        for (int d = 1; d < 8; d <<= 1) {
            int v = __shfl_up_sync(0xffu, inc, d);
            if (lane >= d) inc += v;
        }
        wpre[lane] = inc - s;
        if (lane == 7) sbase = atomicAdd(&d_galloc, inc);
    }
    __syncthreads();
    if (i < NPIL) d_offset[i] = sbase + wpre[w] + (incl - c);
}

// ---------------- pass 1: staged inputs, scalar h, tensor-core a, 128-bit sorted scatter ------
__global__ __launch_bounds__(128) void k_pass1(const float* __restrict__ pts,
                                               const float* __restrict__ fc,
                                               const int* __restrict__ unq) {
    __shared__ ull swp[112];                 // W1f packed pairs
    __shared__ ull st1[16];
    __shared__ __half sWa[32 * 40];          // [n][k] fp16, stride 40 halves
    __shared__ float sT2[32];
    __shared__ __align__(16) __half sh[128 * 72];   // 18 KB staging (72-half = 144B rows)
    int t = threadIdx.x;
    if (t < 112) { float2 w = ((const float2*)d_W1f)[t]; swp[t] = pack2(w.x, w.y); }
    if (t < 16)  { float2 v = ((const float2*)d_t1)[t];  st1[t] = pack2(v.x, v.y); }
    for (int q = t; q < 1024; q += 128) sWa[(q >> 5) * 40 + (q & 31)] = d_W2ah[q];
    if (t < 32) sT2[t] = d_t2[t];

    int lane = t & 31, wid = t >> 5;
    int i = blockIdx.x * 128 + t;

    // destination row for this point (pillar-sorted); -1 for pad threads
    int mypos = (i < NP) ? (d_offset[unq[i]] + d_pos[i]) : -1;

    // ---- coalesced input staging (reuse sh as float scratch) ----
    float* sfin = reinterpret_cast<float*>(sh);
    {
        size_t b5 = (size_t)blockIdx.x * 640;
        size_t l5 = (size_t)NP * 5 - 1;
#pragma unroll
        for (int q = 0; q < 5; q++) {
            size_t o = b5 + q * 128 + t;
            sfin[q * 128 + t] = pts[o > l5 ? l5 : o];
        }
        size_t b3 = (size_t)blockIdx.x * 384;
        size_t l3 = (size_t)NP * 3 - 1;
#pragma unroll
        for (int q = 0; q < 3; q++) {
            size_t o = b3 + q * 128 + t;
            sfin[640 + q * 128 + t] = fc[o > l3 ? l3 : o];
        }
    }
    __syncthreads();

    float f[7];
    f[0] = sfin[640 + t * 3 + 0];
    f[1] = sfin[640 + t * 3 + 1];
    f[2] = sfin[640 + t * 3 + 2];
    f[3] = sfin[t * 5 + 1];
    f[4] = sfin[t * 5 + 2];
    f[5] = sfin[t * 5 + 3];
    f[6] = sfin[t * 5 + 4];
    __syncthreads();                          // inputs consumed; sh reused for rows

    // ---- scalar h = relu(feat @ W1f + t1), f32x2 packed ----
    ull h2[16];
#pragma unroll
    for (int j = 0; j < 16; j++) h2[j] = st1[j];
#pragma unroll
    for (int k = 0; k < 7; k++) {
        ull fk = pack2(f[k], f[k]);
#pragma unroll
        for (int j = 0; j < 16; j++) h2[j] = ffma2(swp[k * 16 + j], fk, h2[j]);
    }
    // relu -> fp16 pairs, staged as 8 x STS.64
    ull* mr64 = reinterpret_cast<ull*>(&sh[t * 72]);
#pragma unroll
    for (int q = 0; q < 8; q++) {
        float x0, x1, x2, x3;
        unpack2(h2[2 * q + 0], x0, x1);
        unpack2(h2[2 * q + 1], x2, x3);
        __half2 pa = __floats2half2_rn(fmaxf(x0, 0.f), fmaxf(x1, 0.f));
        __half2 pb = __floats2half2_rn(fmaxf(x2, 0.f), fmaxf(x3, 0.f));
        u32 ua = *reinterpret_cast<u32*>(&pa);
        u32 ub = *reinterpret_cast<u32*>(&pb);
        mr64[q] = ((ull)ub << 32) | ua;
    }
    __syncwarp();

    // ---- B fragments: W2a fp16 [n][k], once per warp ----
    u32 bfr[4][2][2];
    u32 wb = s2u(sWa);
#pragma unroll
    for (int nt = 0; nt < 4; nt++)
#pragma unroll
        for (int q = 0; q < 2; q++) {
            u32 addr = wb + (((nt * 8 + (lane & 7)) * 40 + q * 16 + ((lane & 8) ? 8 : 0)) << 1);
            asm volatile("ldmatrix.sync.aligned.m8n8.x2.shared.b16 {%0,%1},[%2];"
                         : "=r"(bfr[nt][q][0]), "=r"(bfr[nt][q][1]) : "r"(addr));
        }
    float t2lo[4], t2hi[4];
#pragma unroll
    for (int nt = 0; nt < 4; nt++) {
        t2lo[nt] = sT2[nt * 8 + 2 * (lane & 3)];
        t2hi[nt] = sT2[nt * 8 + 2 * (lane & 3) + 1];
    }

    // ---- tensor-core a = h @ W2a + t2 for this warp's 32 points ----
    u32 shb = s2u(sh);
#pragma unroll
    for (int tile = 0; tile < 2; tile++) {
        int p0 = wid * 32 + tile * 16;
        u32 a[2][4];
#pragma unroll
        for (int q = 0; q < 2; q++) {
            int r = p0 + (lane & 7) + ((lane & 8) ? 8 : 0);
            int colh = q * 16 + ((lane & 16) ? 8 : 0);
            u32 addr = shb + ((r * 72 + colh) << 1);
            asm volatile("ldmatrix.sync.aligned.m8n8.x4.shared.b16 {%0,%1,%2,%3},[%4];"
                         : "=r"(a[q][0]), "=r"(a[q][1]), "=r"(a[q][2]), "=r"(a[q][3])
                         : "r"(addr));
        }
#pragma unroll
        for (int nt = 0; nt < 4; nt++) {
            float d0 = 0.f, d1 = 0.f, d2 = 0.f, d3 = 0.f;
            asm volatile("mma.sync.aligned.m16n8k16.row.col.f32.f16.f16.f32 "
                         "{%0,%1,%2,%3},{%4,%5,%6,%7},{%8,%9},{%0,%1,%2,%3};"
                         : "+f"(d0), "+f"(d1), "+f"(d2), "+f"(d3)
                         : "r"(a[0][0]), "r"(a[0][1]), "r"(a[0][2]), "r"(a[0][3]),
                           "r"(bfr[nt][0][0]), "r"(bfr[nt][0][1]));
            asm volatile("mma.sync.aligned.m16n8k16.row.col.f32.f16.f16.f32 "
                         "{%0,%1,%2,%3},{%4,%5,%6,%7},{%8,%9},{%0,%1,%2,%3};"
                         : "+f"(d0), "+f"(d1), "+f"(d2), "+f"(d3)
                         : "r"(a[1][0]), "r"(a[1][1]), "r"(a[1][2]), "r"(a[1][3]),
                           "r"(bfr[nt][1][0]), "r"(bfr[nt][1][1]));
            int c0 = nt * 8 + 2 * (lane & 3);
            __half2 plo = __floats2half2_rn(d0 + t2lo[nt], d1 + t2hi[nt]);
            __half2 phi = __floats2half2_rn(d2 + t2lo[nt], d3 + t2hi[nt]);
            *reinterpret_cast<u32*>(&sh[(p0 + (lane >> 2)) * 72 + 32 + c0]) =
                *reinterpret_cast<u32*>(&plo);
            *reinterpret_cast<u32*>(&sh[(p0 + 8 + (lane >> 2)) * 72 + 32 + c0]) =
                *reinterpret_cast<u32*>(&phi);
        }
    }
    __syncwarp();

    // ---- 128-bit warp-cooperative scatter: 4 rows / iteration (8 lanes per row) ----
    // staging row stride 144B = 9 x 16B -> every row 16B-aligned
    const char* sbase = reinterpret_cast<const char*>(sh);
    int subrow = lane >> 3;          // 0..3
    int chunk = lane & 7;            // 0..7  (8 x 16B = 128B row)
#pragma unroll
    for (int u = 0; u < 32; u += 4) {
        int pos = __shfl_sync(0xffffffffu, mypos, u + subrow);
        if (pos >= 0) {
            ulonglong2 v = *reinterpret_cast<const ulonglong2*>(
                sbase + (size_t)(wid * 32 + u + subrow) * 144 + chunk * 16);
            *reinterpret_cast<ulonglong2*>(
                reinterpret_cast<char*>(d_ha) + (size_t)pos * 128 + chunk * 16) = v;
        }
    }
}

// ---------------- pass 2: warp/pillar SEQUENTIAL stream over sorted fp16 rows ----------------
__global__ __launch_bounds__(256) void k_pillar(float* __restrict__ out) {
    __shared__ float sWb[32 * 32];
    __shared__ float ssum[8][32];
    __shared__ float smax[8][32];

    int t = threadIdx.x;
    for (int q = t; q < 1024; q += 256) sWb[q] = d_W2f[1024 + q];
    __syncthreads();

    int warp = t >> 5;
    int j = t & 31;
    int p = blockIdx.x * 8 + warp;                 // 3750 * 8 == 30000 exact
    int off = d_offset[p];
    int cnt = d_count[p];
    if (cnt == 0) { out[p * 32 + j] = 0.f; return; }
    const u32* base = d_ha + (size_t)off * 32 + j;

    float sx0 = 0.f, sy0 = 0.f, sx1 = 0.f, sy1 = 0.f;
    float mx = -1e30f, my = -1e30f;
    int r = 0;
    for (; r + 4 <= cnt; r += 4) {
        u32 w0 = base[(r + 0) * 32];
        u32 w1 = base[(r + 1) * 32];
        u32 w2 = base[(r + 2) * 32];
        u32 w3 = base[(r + 3) * 32];
        float2 f0 = __half22float2(*reinterpret_cast<__half2*>(&w0));
        float2 f1 = __half22float2(*reinterpret_cast<__half2*>(&w1));
        float2 f2 = __half22float2(*reinterpret_cast<__half2*>(&w2));
        float2 f3 = __half22float2(*reinterpret_cast<__half2*>(&w3));
        sx0 += f0.x; sy0 += f0.y; mx = fmaxf(mx, f0.x); my = fmaxf(my, f0.y);
        sx1 += f1.x; sy1 += f1.y; mx = fmaxf(mx, f1.x); my = fmaxf(my, f1.y);
        sx0 += f2.x; sy0 += f2.y; mx = fmaxf(mx, f2.x); my = fmaxf(my, f2.y);
        sx1 += f3.x; sy1 += f3.y; mx = fmaxf(mx, f3.x); my = fmaxf(my, f3.y);
    }
    for (; r < cnt; r++) {
        u32 w0 = base[r * 32];
        float2 f0 = __half22float2(*reinterpret_cast<__half2*>(&w0));
        sx0 += f0.x; sy0 += f0.y; mx = fmaxf(mx, f0.x); my = fmaxf(my, f0.y);
    }
    if (j < 16) {
        ssum[warp][2 * j + 0] = sx0 + sx1;
        ssum[warp][2 * j + 1] = sy0 + sy1;
    } else {
        smax[warp][2 * (j - 16) + 0] = mx;
        smax[warp][2 * (j - 16) + 1] = my;
    }
    __syncwarp();

    float pm = 0.f;
#pragma unroll
    for (int k = 0; k < 32; k++) pm = fmaf(ssum[warp][k], sWb[k * 32 + j], pm);
    pm /= (float)cnt;
    out[p * 32 + j] = fmaxf(smax[warp][j] + pm, 0.f);
}

// ---------------- launch ----------------
extern "C" void kernel_launch(void* const* d_in, const int* in_sizes, int n_in,
                              void* d_out, int out_size) {
    const float* points   = (const float*)d_in[0];
    const float* f_center = (const float*)d_in[1];
    const int*   unq      = (const int*)d_in[2];
    const float* W1 = (const float*)d_in[3];
    const float* g1 = (const float*)d_in[4];
    const float* b1 = (const float*)d_in[5];
    const float* m1 = (const float*)d_in[6];
    const float* v1 = (const float*)d_in[7];
    const float* W2 = (const float*)d_in[8];
    const float* g2 = (const float*)d_in[9];
    const float* b2 = (const float*)d_in[10];
    const float* m2 = (const float*)d_in[11];
    const float* v2 = (const float*)d_in[12];

    k_init<<<(NPIL + 255) / 256, 256>>>(W1, g1, b1, m1, v1, W2, g2, b2, m2, v2);
    k_hist<<<(NP / 4 + 255) / 256, 256>>>(unq);
    k_alloc<<<(NPIL + 255) / 256, 256>>>();
    k_pass1<<<(NP + 127) / 128, 128>>>(points, f_center, unq);
    k_pillar<<<NPIL / 8, 256>>>((float*)d_out);
}